// round 8
// baseline (speedup 1.0000x reference)
#include <cuda_runtime.h>

#define B_ 16
#define L_ 2048
#define E_ 256
#define SPLITS 32
#define CHUNK (L_ / SPLITS)   // 64 rows per block

// ---------------- scratch (static device globals; no allocation) ----------------
// NOTE: __align__(16) is required — these are cast to float4*.
__device__ __align__(16) float g_part1[SPLITS][B_][E_];  // per-chunk partial sums of valid x rows
__device__ __align__(16) float g_t[B_ * E_];             // t = Wk^T s
__device__ float g_c[B_];                                // c = s . bk
__device__ __align__(16) float g_part2[SPLITS][B_][E_];  // per-chunk partial y
__device__ float g_Wpart[SPLITS][B_];                    // per-chunk partial sum of w
__device__ int   g_cnt1[B_];                             // completion tickets (self-resetting)
__device__ int   g_cnt2[B_];

// =====================================================================
// K1: chunk partial sums of valid rows; last block per batch computes
//     X -> s = Wq X + len*bq ; t = Wk^T s ; c = s.bk
// =====================================================================
__global__ void __launch_bounds__(256) k_phase1(
    const float* __restrict__ x, const int* __restrict__ lengths,
    const float* __restrict__ Wq, const float* __restrict__ bq,
    const float* __restrict__ Wk, const float* __restrict__ bk)
{
    const int si = blockIdx.x, b = blockIdx.y, tid = threadIdx.x;
    const int len = lengths[b];
    const int start = si * CHUNK;
    const int end = min(start + CHUNK, len);

    if (end > start) {
        // 4 row-lanes x 64 col-lanes (float4 per col-lane)
        const int rl = tid >> 6;       // 0..3
        const int cl = tid & 63;       // 0..63
        float4 acc = make_float4(0.f, 0.f, 0.f, 0.f);
        const float4* base = (const float4*)(x + (size_t)b * L_ * E_) + cl;
        int l = start + rl;
        for (; l + 4 < end; l += 8) {  // two rows in flight
            float4 v0 = base[(size_t)l * (E_ / 4)];
            float4 v1 = base[(size_t)(l + 4) * (E_ / 4)];
            acc.x += v0.x + v1.x; acc.y += v0.y + v1.y;
            acc.z += v0.z + v1.z; acc.w += v0.w + v1.w;
        }
        if (l < end) {
            float4 v0 = base[(size_t)l * (E_ / 4)];
            acc.x += v0.x; acc.y += v0.y; acc.z += v0.z; acc.w += v0.w;
        }
        __shared__ __align__(16) float4 red[4][64];
        red[rl][cl] = acc;
        __syncthreads();
        if (rl == 0) {
            float4 a = red[0][cl], p = red[1][cl], q = red[2][cl], r = red[3][cl];
            float4 s;
            s.x = a.x + p.x + q.x + r.x;
            s.y = a.y + p.y + q.y + r.y;
            s.z = a.z + p.z + q.z + r.z;
            s.w = a.w + p.w + q.w + r.w;
            ((float4*)g_part1[si][b])[cl] = s;
        }
        __threadfence();  // make partials visible before ticket
    }
    __syncthreads();

    __shared__ bool isLast;
    if (tid == 0) {
        int t = atomicAdd(&g_cnt1[b], 1);
        isLast = (t == SPLITS - 1);
        if (isLast) g_cnt1[b] = 0;  // self-reset for graph replay
    }
    __syncthreads();
    if (!isLast) return;

    // ---- reduction + tiny matvecs (one block per batch) ----
    const int nact = min(SPLITS, (len + CHUNK - 1) / CHUNK);
    __shared__ __align__(16) float sX[E_];
    __shared__ float sS[E_];
    float xv = 0.f;
    for (int s = 0; s < nact; ++s) xv += g_part1[s][b][tid];
    sX[tid] = xv;
    __syncthreads();

    // s[f] = Wq[f,:].X + len*bq[f]
    float acc = 0.f;
    const float4* wq4 = (const float4*)(Wq + (size_t)tid * E_);
    const float4* x4  = (const float4*)sX;
#pragma unroll 8
    for (int i = 0; i < E_ / 4; ++i) {
        float4 w = wq4[i], v = x4[i];
        acc += w.x * v.x + w.y * v.y + w.z * v.z + w.w * v.w;
    }
    sS[tid] = acc + (float)len * bq[tid];
    __syncthreads();

    // t[e] = sum_f s[f] * Wk[f,e]  (coalesced across threads)
    float tv = 0.f;
#pragma unroll 8
    for (int f = 0; f < E_; ++f)
        tv += sS[f] * Wk[(size_t)f * E_ + tid];
    g_t[b * E_ + tid] = tv;

    // c = s . bk
    sX[tid] = sS[tid] * bk[tid];
    __syncthreads();
    for (int s = E_ / 2; s > 0; s >>= 1) {
        if (tid < s) sX[tid] += sX[tid + s];
        __syncthreads();
    }
    if (tid == 0) g_c[b] = sX[0];
}

// =====================================================================
// K2: pass over x: w_l = t.x_l + c ; y += w_l x_l ; W += w_l  (chunk
//     partials), last block per batch reduces and emits
//     out[b] = (Wv y + W*bv) / L
// =====================================================================
__global__ void __launch_bounds__(256) k_phase2(
    const float* __restrict__ x, const int* __restrict__ lengths,
    const float* __restrict__ Wv, const float* __restrict__ bv,
    float* __restrict__ out)
{
    const int si = blockIdx.x, b = blockIdx.y, tid = threadIdx.x;
    const int warp = tid >> 5, lane = tid & 31;
    const int len = lengths[b];
    const int start = si * CHUNK;
    const int end = min(start + CHUNK, len);

    __shared__ __align__(16) float ys[E_];
    __shared__ float wsh;

    if (end > start) {
        ys[tid] = 0.f;
        if (tid == 0) wsh = 0.f;
        __syncthreads();

        const float4* t4 = (const float4*)(g_t + b * E_);
        const float4 ta = t4[lane];
        const float4 tb = t4[32 + lane];
        const float c = g_c[b];

        float4 ya = make_float4(0.f, 0.f, 0.f, 0.f);
        float4 yb = make_float4(0.f, 0.f, 0.f, 0.f);
        float wacc = 0.f;

        // 8 warps; warp handles rows start+warp, +8, ... ; unroll x2
        for (int l0 = start + warp; l0 < end; l0 += 16) {
            const int l1 = l0 + 8;
            const bool has1 = (l1 < end);          // warp-uniform
            const float4* xr0 = (const float4*)(x + ((size_t)b * L_ + l0) * E_);
            float4 va0 = xr0[lane], vb0 = xr0[32 + lane];
            float4 va1, vb1;
            float p0 = va0.x * ta.x + va0.y * ta.y + va0.z * ta.z + va0.w * ta.w
                     + vb0.x * tb.x + vb0.y * tb.y + vb0.z * tb.z + vb0.w * tb.w;
            float p1 = 0.f;
            if (has1) {
                const float4* xr1 = (const float4*)(x + ((size_t)b * L_ + l1) * E_);
                va1 = xr1[lane]; vb1 = xr1[32 + lane];
                p1 = va1.x * ta.x + va1.y * ta.y + va1.z * ta.z + va1.w * ta.w
                   + vb1.x * tb.x + vb1.y * tb.y + vb1.z * tb.z + vb1.w * tb.w;
            }
#pragma unroll
            for (int off = 16; off > 0; off >>= 1) {   // two independent chains
                p0 += __shfl_xor_sync(0xffffffffu, p0, off);
                p1 += __shfl_xor_sync(0xffffffffu, p1, off);
            }
            const float w0 = p0 + c;
            ya.x += w0 * va0.x; ya.y += w0 * va0.y; ya.z += w0 * va0.z; ya.w += w0 * va0.w;
            yb.x += w0 * vb0.x; yb.y += w0 * vb0.y; yb.z += w0 * vb0.z; yb.w += w0 * vb0.w;
            float wsum = w0;
            if (has1) {
                const float w1 = p1 + c;
                ya.x += w1 * va1.x; ya.y += w1 * va1.y; ya.z += w1 * va1.z; ya.w += w1 * va1.w;
                yb.x += w1 * vb1.x; yb.y += w1 * vb1.y; yb.z += w1 * vb1.z; yb.w += w1 * vb1.w;
                wsum += w1;
            }
            if (lane == 0) wacc += wsum;
        }

        const int e0 = 4 * lane;
        atomicAdd(&ys[e0 + 0], ya.x); atomicAdd(&ys[e0 + 1], ya.y);
        atomicAdd(&ys[e0 + 2], ya.z); atomicAdd(&ys[e0 + 3], ya.w);
        atomicAdd(&ys[128 + e0 + 0], yb.x); atomicAdd(&ys[128 + e0 + 1], yb.y);
        atomicAdd(&ys[128 + e0 + 2], yb.z); atomicAdd(&ys[128 + e0 + 3], yb.w);
        if (lane == 0) atomicAdd(&wsh, wacc);
        __syncthreads();

        g_part2[si][b][tid] = ys[tid];
        if (tid == 0) g_Wpart[si][b] = wsh;
        __threadfence();
    }
    __syncthreads();

    __shared__ bool isLast;
    if (tid == 0) {
        int t = atomicAdd(&g_cnt2[b], 1);
        isLast = (t == SPLITS - 1);
        if (isLast) g_cnt2[b] = 0;  // self-reset for graph replay
    }
    __syncthreads();
    if (!isLast) return;

    // ---- final reduction + Wv matvec (one block per batch) ----
    const int nact = min(SPLITS, (len + CHUNK - 1) / CHUNK);
    float yacc = 0.f;
    for (int s = 0; s < nact; ++s) yacc += g_part2[s][b][tid];
    ys[tid] = yacc;
    if (tid == 0) {
        float Wt = 0.f;
        for (int s = 0; s < nact; ++s) Wt += g_Wpart[s][b];
        wsh = Wt;
    }
    __syncthreads();

    float acc = 0.f;
    const float4* wv4 = (const float4*)(Wv + (size_t)tid * E_);
    const float4* y4  = (const float4*)ys;
#pragma unroll 8
    for (int i = 0; i < E_ / 4; ++i) {
        float4 w = wv4[i], v = y4[i];
        acc += w.x * v.x + w.y * v.y + w.z * v.z + w.w * v.w;
    }
    out[b * E_ + tid] = (acc + wsh * bv[tid]) * (1.0f / (float)L_);
}

extern "C" void kernel_launch(void* const* d_in, const int* in_sizes, int n_in,
                              void* d_out, int out_size) {
    const float* x       = (const float*)d_in[0];
    const int*   lengths = (const int*)d_in[1];
    const float* Wq      = (const float*)d_in[2];
    const float* bq      = (const float*)d_in[3];
    const float* Wk      = (const float*)d_in[4];
    const float* bk      = (const float*)d_in[5];
    const float* Wv      = (const float*)d_in[6];
    const float* bv      = (const float*)d_in[7];
    float* out = (float*)d_out;

    k_phase1<<<dim3(SPLITS, B_), 256>>>(x, lengths, Wq, bq, Wk, bk);
    k_phase2<<<dim3(SPLITS, B_), 256>>>(x, lengths, Wv, bv, out);
}

// round 10
// speedup vs baseline: 1.0279x; 1.0279x over previous
#include <cuda_runtime.h>

#define B_ 16
#define L_ 2048
#define E_ 256
#define SPLITS 64
#define CHUNK (L_ / SPLITS)   // 32 rows per block

// ---------------- scratch (static device globals; no allocation) ----------------
__device__ __align__(16) float g_part1[SPLITS][B_][E_];  // per-chunk partial sums of valid x rows
__device__ __align__(16) float g_t[B_ * E_];             // t = Wk^T s
__device__ float g_c[B_];                                // c = s . bk
__device__ __align__(16) float g_part2[SPLITS][B_][E_];  // per-chunk partial y
__device__ float g_Wpart[SPLITS][B_];                    // per-chunk partial sum of w
__device__ int   g_cnt1[B_];                             // completion tickets (self-resetting)
__device__ int   g_cnt2[B_];

__device__ __forceinline__ float dot4(float4 a, float4 b) {
    return a.x * b.x + a.y * b.y + a.z * b.z + a.w * b.w;
}

// =====================================================================
// K1: chunk partial sums of valid rows; last block per batch computes
//     X -> s = Wq X + len*bq ; t = Wk^T s ; c = s.bk
// =====================================================================
__global__ void __launch_bounds__(256) k_phase1(
    const float* __restrict__ x, const int* __restrict__ lengths,
    const float* __restrict__ Wq, const float* __restrict__ bq,
    const float* __restrict__ Wk, const float* __restrict__ bk)
{
    const int si = blockIdx.x, b = blockIdx.y, tid = threadIdx.x;
    const int len = lengths[b];
    const int start = si * CHUNK;
    const int end = min(start + CHUNK, len);
    const int rows = end - start;

    if (rows > 0) {
        // 4 row-lanes x 64 col-lanes (float4 per col-lane); 8 rows per thread
        const int rl = tid >> 6;       // 0..3
        const int cl = tid & 63;       // 0..63
        const float4* base = (const float4*)(x + (size_t)b * L_ * E_) + cl;
        float4 acc = make_float4(0.f, 0.f, 0.f, 0.f);
        if (rows == CHUNK) {
            // full chunk: 8 fully independent loads in flight
            float4 v[8];
#pragma unroll
            for (int k = 0; k < 8; ++k)
                v[k] = base[(size_t)(start + rl + 4 * k) * (E_ / 4)];
            float4 s01, s23, s45, s67, sA, sB;
            s01.x=v[0].x+v[1].x; s01.y=v[0].y+v[1].y; s01.z=v[0].z+v[1].z; s01.w=v[0].w+v[1].w;
            s23.x=v[2].x+v[3].x; s23.y=v[2].y+v[3].y; s23.z=v[2].z+v[3].z; s23.w=v[2].w+v[3].w;
            s45.x=v[4].x+v[5].x; s45.y=v[4].y+v[5].y; s45.z=v[4].z+v[5].z; s45.w=v[4].w+v[5].w;
            s67.x=v[6].x+v[7].x; s67.y=v[6].y+v[7].y; s67.z=v[6].z+v[7].z; s67.w=v[6].w+v[7].w;
            sA.x=s01.x+s23.x; sA.y=s01.y+s23.y; sA.z=s01.z+s23.z; sA.w=s01.w+s23.w;
            sB.x=s45.x+s67.x; sB.y=s45.y+s67.y; sB.z=s45.z+s67.z; sB.w=s45.w+s67.w;
            acc.x=sA.x+sB.x; acc.y=sA.y+sB.y; acc.z=sA.z+sB.z; acc.w=sA.w+sB.w;
        } else {
            for (int l = start + rl; l < end; l += 4) {
                float4 v0 = base[(size_t)l * (E_ / 4)];
                acc.x += v0.x; acc.y += v0.y; acc.z += v0.z; acc.w += v0.w;
            }
        }
        __shared__ __align__(16) float4 red[4][64];
        red[rl][cl] = acc;
        __syncthreads();
        if (rl == 0) {
            float4 a = red[0][cl], p = red[1][cl], q = red[2][cl], r = red[3][cl];
            float4 s;
            s.x = a.x + p.x + q.x + r.x;
            s.y = a.y + p.y + q.y + r.y;
            s.z = a.z + p.z + q.z + r.z;
            s.w = a.w + p.w + q.w + r.w;
            ((float4*)g_part1[si][b])[cl] = s;
        }
        __threadfence();  // release this thread's writes before the ticket
    }
    __syncthreads();

    __shared__ bool isLast;
    if (tid == 0) {
        int t = atomicAdd(&g_cnt1[b], 1);
        isLast = (t == SPLITS - 1);
        if (isLast) g_cnt1[b] = 0;  // self-reset for graph replay
    }
    __syncthreads();
    if (!isLast) return;

    // ---- reduction + tiny matvecs (one block per batch) ----
    const int nact = min(SPLITS, (len + CHUNK - 1) / CHUNK);
    __shared__ __align__(16) float sX[E_];
    __shared__ float sS[E_];
    float xv = 0.f;
#pragma unroll 8
    for (int s = 0; s < nact; ++s) xv += g_part1[s][b][tid];
    sX[tid] = xv;
    __syncthreads();

    // s[f] = Wq[f,:].X + len*bq[f]   (thread = output f)
    {
        float acc = 0.f;
        const float4* wq4 = (const float4*)(Wq + (size_t)tid * E_);
        const float4* x4  = (const float4*)sX;
#pragma unroll 16
        for (int i = 0; i < E_ / 4; ++i)
            acc += dot4(wq4[i], x4[i]);
        sS[tid] = acc + (float)len * bq[tid];
    }
    __syncthreads();

    // t[e] = sum_f s[f] * Wk[f,e]  — 2D split: 64 e-groups (float4) x 4 f-groups
    {
        const int eg = tid & 63;       // float4 column group: e = 4*eg..4*eg+3
        const int fg = tid >> 6;       // 0..3, covers f in [64*fg, 64*fg+64)
        const float4* wk4 = (const float4*)Wk;
        float4 tv = make_float4(0.f, 0.f, 0.f, 0.f);
#pragma unroll 8
        for (int j = 0; j < 64; ++j) {
            const int f = fg * 64 + j;
            const float sv = sS[f];
            float4 wv = wk4[(size_t)f * (E_ / 4) + eg];
            tv.x += sv * wv.x; tv.y += sv * wv.y; tv.z += sv * wv.z; tv.w += sv * wv.w;
        }
        __shared__ __align__(16) float4 tpart[4][64];
        tpart[fg][eg] = tv;
        __syncthreads();
        if (tid < 64) {
            float4 a = tpart[0][tid], p = tpart[1][tid], q = tpart[2][tid], r = tpart[3][tid];
            float4 t0;
            t0.x = a.x + p.x + q.x + r.x;
            t0.y = a.y + p.y + q.y + r.y;
            t0.z = a.z + p.z + q.z + r.z;
            t0.w = a.w + p.w + q.w + r.w;
            ((float4*)(g_t + b * E_))[tid] = t0;
        }
    }

    // c = s . bk  (tree reduce, reuse sX)
    __syncthreads();
    sX[tid] = sS[tid] * bk[tid];
    __syncthreads();
    for (int s = E_ / 2; s > 0; s >>= 1) {
        if (tid < s) sX[tid] += sX[tid + s];
        __syncthreads();
    }
    if (tid == 0) g_c[b] = sX[0];
}

// =====================================================================
// K2: stage chunk to SMEM (MLP=8/thread), compute w + y from SMEM,
//     last block per batch reduces and emits out[b] = (Wv y + W*bv)/L
// =====================================================================
__global__ void __launch_bounds__(256) k_phase2(
    const float* __restrict__ x, const int* __restrict__ lengths,
    const float* __restrict__ Wv, const float* __restrict__ bv,
    float* __restrict__ out)
{
    const int si = blockIdx.x, b = blockIdx.y, tid = threadIdx.x;
    const int warp = tid >> 5, lane = tid & 31;
    const int len = lengths[b];
    const int start = si * CHUNK;
    const int end = min(start + CHUNK, len);
    const int rows = end - start;

    __shared__ __align__(16) float sx[CHUNK * E_];   // 32 KB staged tile (reused in tail)
    __shared__ float shw[CHUNK];
    __shared__ float wtot;

    if (rows > 0) {
        // ---- stage: 2048 float4, 8 independent loads per thread ----
        const float4* src = (const float4*)(x + ((size_t)b * L_ + start) * E_);
        float4* dst = (float4*)sx;
#pragma unroll
        for (int i = 0; i < 8; ++i) {
            const int idx = tid + 256 * i;        // [0, 2048)
            const int row = idx >> 6;             // 64 float4 per row
            float4 v = make_float4(0.f, 0.f, 0.f, 0.f);
            if (row < rows) v = src[idx];
            dst[idx] = v;                         // zero-pad invalid rows
        }
        __syncthreads();

        // ---- w-dots from SMEM: warp wp handles rows wp, wp+8, wp+16, wp+24 ----
        {
            const float4* t4 = (const float4*)(g_t + b * E_);
            const float4 ta = t4[lane];
            const float4 tb = t4[32 + lane];
            const float c = g_c[b];
            float p0, p1, p2, p3;
            {
                const float4* r0 = (const float4*)(sx + (warp +  0) * E_);
                const float4* r1 = (const float4*)(sx + (warp +  8) * E_);
                const float4* r2 = (const float4*)(sx + (warp + 16) * E_);
                const float4* r3 = (const float4*)(sx + (warp + 24) * E_);
                p0 = dot4(r0[lane], ta) + dot4(r0[32 + lane], tb);
                p1 = dot4(r1[lane], ta) + dot4(r1[32 + lane], tb);
                p2 = dot4(r2[lane], ta) + dot4(r2[32 + lane], tb);
                p3 = dot4(r3[lane], ta) + dot4(r3[32 + lane], tb);
            }
#pragma unroll
            for (int off = 16; off > 0; off >>= 1) {   // 4 interleaved chains
                p0 += __shfl_xor_sync(0xffffffffu, p0, off);
                p1 += __shfl_xor_sync(0xffffffffu, p1, off);
                p2 += __shfl_xor_sync(0xffffffffu, p2, off);
                p3 += __shfl_xor_sync(0xffffffffu, p3, off);
            }
            if (lane == 0) {
                shw[warp +  0] = p0 + c;
                shw[warp +  8] = p1 + c;
                shw[warp + 16] = p2 + c;
                shw[warp + 24] = p3 + c;
            }
        }
        __syncthreads();

        // ---- y[e] = sum_l w_l * x_l[e]; thread owns column e = tid ----
        {
            float y = 0.f;
#pragma unroll
            for (int l = 0; l < CHUNK; ++l)
                y += shw[l] * sx[l * E_ + tid];   // invalid rows: sx==0
            g_part2[si][b][tid] = y;
        }
        // ---- partial sum of w over VALID rows (warp 0) ----
        if (warp == 0) {
            float v = (lane < rows) ? shw[lane] : 0.f;   // CHUNK == 32 lanes
#pragma unroll
            for (int off = 16; off > 0; off >>= 1)
                v += __shfl_xor_sync(0xffffffffu, v, off);
            if (lane == 0) g_Wpart[si][b] = v;
        }
        __threadfence();
    }
    __syncthreads();

    __shared__ bool isLast;
    if (tid == 0) {
        int t = atomicAdd(&g_cnt2[b], 1);
        isLast = (t == SPLITS - 1);
        if (isLast) g_cnt2[b] = 0;  // self-reset for graph replay
    }
    __syncthreads();
    if (!isLast) return;

    // ---- final reduction + Wv matvec (one block per batch) ----
    const int nact = min(SPLITS, (len + CHUNK - 1) / CHUNK);
    {
        float yv = 0.f;
#pragma unroll 8
        for (int s = 0; s < nact; ++s) yv += g_part2[s][b][tid];
        sx[tid] = yv;                               // reuse staging smem as ys[256]
    }
    if (warp == 0) {                                // warp-parallel W gather
        float W = 0.f;
        for (int s = lane; s < nact; s += 32) W += g_Wpart[s][b];
#pragma unroll
        for (int off = 16; off > 0; off >>= 1)
            W += __shfl_xor_sync(0xffffffffu, W, off);
        if (lane == 0) wtot = W;
    }
    __syncthreads();

    {
        float acc = 0.f;
        const float4* wv4 = (const float4*)(Wv + (size_t)tid * E_);
        const float4* y4  = (const float4*)sx;
#pragma unroll 16
        for (int i = 0; i < E_ / 4; ++i)
            acc += dot4(wv4[i], y4[i]);
        out[b * E_ + tid] = (acc + wtot * bv[tid]) * (1.0f / (float)L_);
    }
}

extern "C" void kernel_launch(void* const* d_in, const int* in_sizes, int n_in,
                              void* d_out, int out_size) {
    const float* x       = (const float*)d_in[0];
    const int*   lengths = (const int*)d_in[1];
    const float* Wq      = (const float*)d_in[2];
    const float* bq      = (const float*)d_in[3];
    const float* Wk      = (const float*)d_in[4];
    const float* bk      = (const float*)d_in[5];
    const float* Wv      = (const float*)d_in[6];
    const float* bv      = (const float*)d_in[7];
    float* out = (float*)d_out;

    k_phase1<<<dim3(SPLITS, B_), 256>>>(x, lengths, Wq, bq, Wk, bk);
    k_phase2<<<dim3(SPLITS, B_), 256>>>(x, lengths, Wv, bv, out);
}

// round 14
// speedup vs baseline: 1.9522x; 1.8992x over previous
#include <cuda_runtime.h>

#define B_ 16
#define L_ 2048
#define E_ 256
#define SPLITS 64
#define CHUNK (L_ / SPLITS)   // 32 rows per block

// ---------------- scratch (static device globals; no allocation) ----------------
__device__ __align__(16) float g_part1[SPLITS][B_][E_];  // per-chunk partial sums of valid x rows
__device__ __align__(16) float g_t[B_ * E_];             // t = Wk^T s
__device__ float g_c[B_];                                // c = s . bk
__device__ __align__(16) float g_part2[SPLITS][B_][E_];  // per-chunk partial y
__device__ float g_Wpart[SPLITS][B_];                    // per-chunk partial sum of w

__device__ __forceinline__ float dot4(float4 a, float4 b) {
    return a.x * b.x + a.y * b.y + a.z * b.z + a.w * b.w;
}

// =====================================================================
// K1: pure stream — chunk partial sums of valid rows. No sync machinery.
// =====================================================================
__global__ void __launch_bounds__(256) k1_stream(
    const float* __restrict__ x, const int* __restrict__ lengths)
{
    const int si = blockIdx.x, b = blockIdx.y, tid = threadIdx.x;
    const int len = lengths[b];
    const int start = si * CHUNK;
    const int end = min(start + CHUNK, len);
    const int rows = end - start;
    if (rows <= 0) return;                 // inactive chunk: combine never reads it

    // 4 row-lanes x 64 col-lanes (float4 per col-lane); 8 rows per row-lane
    const int rl = tid >> 6;       // 0..3
    const int cl = tid & 63;       // 0..63
    const float4* base = (const float4*)(x + (size_t)b * L_ * E_) + cl;
    float4 acc = make_float4(0.f, 0.f, 0.f, 0.f);
    if (rows == CHUNK) {
        float4 v[8];
#pragma unroll
        for (int k = 0; k < 8; ++k)        // 8 fully independent loads in flight
            v[k] = base[(size_t)(start + rl + 4 * k) * (E_ / 4)];
#pragma unroll
        for (int k = 0; k < 8; ++k) {
            acc.x += v[k].x; acc.y += v[k].y; acc.z += v[k].z; acc.w += v[k].w;
        }
    } else {
        for (int l = start + rl; l < end; l += 4) {
            float4 v0 = base[(size_t)l * (E_ / 4)];
            acc.x += v0.x; acc.y += v0.y; acc.z += v0.z; acc.w += v0.w;
        }
    }
    __shared__ __align__(16) float4 red[4][64];
    red[rl][cl] = acc;
    __syncthreads();
    if (rl == 0) {
        float4 a = red[0][cl], p = red[1][cl], q = red[2][cl], r = red[3][cl];
        float4 s;
        s.x = a.x + p.x + q.x + r.x;
        s.y = a.y + p.y + q.y + r.y;
        s.z = a.z + p.z + q.z + r.z;
        s.w = a.w + p.w + q.w + r.w;
        ((float4*)g_part1[si][b])[cl] = s;
    }
}

// =====================================================================
// K1b: one block per batch — X -> s = Wq X + len*bq ; t = Wk^T s ; c = s.bk
// =====================================================================
__global__ void __launch_bounds__(256) k1_combine(
    const int* __restrict__ lengths,
    const float* __restrict__ Wq, const float* __restrict__ bq,
    const float* __restrict__ Wk, const float* __restrict__ bk)
{
    const int b = blockIdx.x, tid = threadIdx.x;
    const int len = lengths[b];
    const int nact = min(SPLITS, (len + CHUNK - 1) / CHUNK);

    __shared__ __align__(16) float sX[E_];
    __shared__ float sS[E_];
    {
        float xv = 0.f;
#pragma unroll 8
        for (int s = 0; s < nact; ++s) xv += g_part1[s][b][tid];
        sX[tid] = xv;
    }
    __syncthreads();

    // s[f] = Wq[f,:].X + len*bq[f]
    {
        float acc = 0.f;
        const float4* wq4 = (const float4*)(Wq + (size_t)tid * E_);
        const float4* x4  = (const float4*)sX;
#pragma unroll 16
        for (int i = 0; i < E_ / 4; ++i)
            acc += dot4(wq4[i], x4[i]);
        sS[tid] = acc + (float)len * bq[tid];
    }
    __syncthreads();

    // t[e] = sum_f s[f]*Wk[f,e] — 2D split: 64 e-groups (float4) x 4 f-groups
    {
        const int eg = tid & 63;
        const int fg = tid >> 6;
        const float4* wk4 = (const float4*)Wk;
        float4 tv = make_float4(0.f, 0.f, 0.f, 0.f);
#pragma unroll 8
        for (int j = 0; j < 64; ++j) {
            const int f = fg * 64 + j;
            const float sv = sS[f];
            float4 wv = wk4[(size_t)f * (E_ / 4) + eg];
            tv.x += sv * wv.x; tv.y += sv * wv.y; tv.z += sv * wv.z; tv.w += sv * wv.w;
        }
        __shared__ __align__(16) float4 tpart[4][64];
        tpart[fg][eg] = tv;
        __syncthreads();
        if (tid < 64) {
            float4 a = tpart[0][tid], p = tpart[1][tid], q = tpart[2][tid], r = tpart[3][tid];
            float4 t0;
            t0.x = a.x + p.x + q.x + r.x;
            t0.y = a.y + p.y + q.y + r.y;
            t0.z = a.z + p.z + q.z + r.z;
            t0.w = a.w + p.w + q.w + r.w;
            ((float4*)(g_t + b * E_))[tid] = t0;
        }
    }

    // c = s . bk
    __syncthreads();
    sX[tid] = sS[tid] * bk[tid];
    __syncthreads();
    for (int s = E_ / 2; s > 0; s >>= 1) {
        if (tid < s) sX[tid] += sX[tid + s];
        __syncthreads();
    }
    if (tid == 0) g_c[b] = sX[0];
}

// =====================================================================
// K2: stage chunk to SMEM (MLP=8/thread), compute w + y partials. No sync.
// =====================================================================
__global__ void __launch_bounds__(256) k2_stream(
    const float* __restrict__ x, const int* __restrict__ lengths)
{
    const int si = blockIdx.x, b = blockIdx.y, tid = threadIdx.x;
    const int warp = tid >> 5, lane = tid & 31;
    const int len = lengths[b];
    const int start = si * CHUNK;
    const int end = min(start + CHUNK, len);
    const int rows = end - start;
    if (rows <= 0) return;

    __shared__ __align__(16) float sx[CHUNK * E_];   // 32 KB staged tile
    __shared__ float shw[CHUNK];

    // ---- stage: 2048 float4, 8 independent loads per thread ----
    {
        const float4* src = (const float4*)(x + ((size_t)b * L_ + start) * E_);
        float4* dst = (float4*)sx;
#pragma unroll
        for (int i = 0; i < 8; ++i) {
            const int idx = tid + 256 * i;        // [0, 2048)
            const int row = idx >> 6;             // 64 float4 per row
            float4 v = make_float4(0.f, 0.f, 0.f, 0.f);
            if (row < rows) v = src[idx];
            dst[idx] = v;                         // zero-pad invalid rows
        }
    }
    __syncthreads();

    // ---- w-dots from SMEM: warp wp handles rows wp, wp+8, wp+16, wp+24 ----
    {
        const float4* t4 = (const float4*)(g_t + b * E_);
        const float4 ta = t4[lane];
        const float4 tb = t4[32 + lane];
        const float c = g_c[b];
        float p0, p1, p2, p3;
        {
            const float4* r0 = (const float4*)(sx + (warp +  0) * E_);
            const float4* r1 = (const float4*)(sx + (warp +  8) * E_);
            const float4* r2 = (const float4*)(sx + (warp + 16) * E_);
            const float4* r3 = (const float4*)(sx + (warp + 24) * E_);
            p0 = dot4(r0[lane], ta) + dot4(r0[32 + lane], tb);
            p1 = dot4(r1[lane], ta) + dot4(r1[32 + lane], tb);
            p2 = dot4(r2[lane], ta) + dot4(r2[32 + lane], tb);
            p3 = dot4(r3[lane], ta) + dot4(r3[32 + lane], tb);
        }
#pragma unroll
        for (int off = 16; off > 0; off >>= 1) {   // 4 interleaved chains
            p0 += __shfl_xor_sync(0xffffffffu, p0, off);
            p1 += __shfl_xor_sync(0xffffffffu, p1, off);
            p2 += __shfl_xor_sync(0xffffffffu, p2, off);
            p3 += __shfl_xor_sync(0xffffffffu, p3, off);
        }
        if (lane == 0) {
            shw[warp +  0] = p0 + c;
            shw[warp +  8] = p1 + c;
            shw[warp + 16] = p2 + c;
            shw[warp + 24] = p3 + c;
        }
    }
    __syncthreads();

    // ---- y[e] = sum_l w_l * x_l[e]; thread owns column e = tid ----
    {
        float y = 0.f;
#pragma unroll
        for (int l = 0; l < CHUNK; ++l)
            y += shw[l] * sx[l * E_ + tid];       // invalid rows: sx==0
        g_part2[si][b][tid] = y;
    }
    // ---- partial sum of w over VALID rows (warp 0; CHUNK == 32 lanes) ----
    if (warp == 0) {
        float v = (lane < rows) ? shw[lane] : 0.f;
#pragma unroll
        for (int off = 16; off > 0; off >>= 1)
            v += __shfl_xor_sync(0xffffffffu, v, off);
        if (lane == 0) g_Wpart[si][b] = v;
    }
}

// =====================================================================
// K2b: one block per batch — out[b] = (Wv y + W*bv) / L
// =====================================================================
__global__ void __launch_bounds__(256) k2_combine(
    const int* __restrict__ lengths,
    const float* __restrict__ Wv, const float* __restrict__ bv,
    float* __restrict__ out)
{
    const int b = blockIdx.x, tid = threadIdx.x;
    const int warp = tid >> 5, lane = tid & 31;
    const int len = lengths[b];
    const int nact = min(SPLITS, (len + CHUNK - 1) / CHUNK);

    __shared__ __align__(16) float ys[E_];
    __shared__ float wtot;
    {
        float yv = 0.f;
#pragma unroll 8
        for (int s = 0; s < nact; ++s) yv += g_part2[s][b][tid];
        ys[tid] = yv;
    }
    if (warp == 0) {
        float W = 0.f;
        for (int s = lane; s < nact; s += 32) W += g_Wpart[s][b];
#pragma unroll
        for (int off = 16; off > 0; off >>= 1)
            W += __shfl_xor_sync(0xffffffffu, W, off);
        if (lane == 0) wtot = W;
    }
    __syncthreads();

    float acc = 0.f;
    const float4* wv4 = (const float4*)(Wv + (size_t)tid * E_);
    const float4* y4  = (const float4*)ys;
#pragma unroll 16
    for (int i = 0; i < E_ / 4; ++i)
        acc += dot4(wv4[i], y4[i]);
    out[b * E_ + tid] = (acc + wtot * bv[tid]) * (1.0f / (float)L_);
}

extern "C" void kernel_launch(void* const* d_in, const int* in_sizes, int n_in,
                              void* d_out, int out_size) {
    const float* x       = (const float*)d_in[0];
    const int*   lengths = (const int*)d_in[1];
    const float* Wq      = (const float*)d_in[2];
    const float* bq      = (const float*)d_in[3];
    const float* Wk      = (const float*)d_in[4];
    const float* bk      = (const float*)d_in[5];
    const float* Wv      = (const float*)d_in[6];
    const float* bv      = (const float*)d_in[7];
    float* out = (float*)d_out;

    k1_stream <<<dim3(SPLITS, B_), 256>>>(x, lengths);
    k1_combine<<<B_, 256>>>(lengths, Wq, bq, Wk, bk);
    k2_stream <<<dim3(SPLITS, B_), 256>>>(x, lengths);
    k2_combine<<<B_, 256>>>(lengths, Wv, bv, out);
}

// round 17
// speedup vs baseline: 2.2598x; 1.1576x over previous
#include <cuda_runtime.h>

#define B_ 16
#define L_ 2048
#define E_ 256
#define SPLITS 64
#define CHUNK (L_ / SPLITS)   // 32 rows per block

// ---------------- scratch (static device globals; no allocation) ----------------
__device__ __align__(16) float g_part1[SPLITS][B_][E_];  // per-chunk partial sums of valid x rows
__device__ __align__(16) float g_t[B_ * E_];             // t = Wk^T s
__device__ float g_c[B_];                                // c = s . bk
__device__ __align__(16) float g_part2[SPLITS][B_][E_];  // per-chunk partial y
__device__ float g_Wpart[SPLITS][B_];                    // per-chunk partial sum of w

__device__ __forceinline__ float dot4(float4 a, float4 b) {
    return a.x * b.x + a.y * b.y + a.z * b.z + a.w * b.w;
}

// =====================================================================
// K1: pure stream — chunk partial sums of valid rows. No sync machinery.
// =====================================================================
__global__ void __launch_bounds__(256) k1_stream(
    const float* __restrict__ x, const int* __restrict__ lengths)
{
    const int si = blockIdx.x, b = blockIdx.y, tid = threadIdx.x;
    const int len = lengths[b];
    const int start = si * CHUNK;
    const int end = min(start + CHUNK, len);
    const int rows = end - start;
    if (rows <= 0) return;                 // inactive chunk: combine never reads it

    // 4 row-lanes x 64 col-lanes (float4 per col-lane); 8 rows per row-lane
    const int rl = tid >> 6;       // 0..3
    const int cl = tid & 63;       // 0..63
    const float4* base = (const float4*)(x + (size_t)b * L_ * E_) + cl;
    float4 acc = make_float4(0.f, 0.f, 0.f, 0.f);
    if (rows == CHUNK) {
        float4 v[8];
#pragma unroll
        for (int k = 0; k < 8; ++k)        // 8 fully independent loads in flight
            v[k] = base[(size_t)(start + rl + 4 * k) * (E_ / 4)];
#pragma unroll
        for (int k = 0; k < 8; ++k) {
            acc.x += v[k].x; acc.y += v[k].y; acc.z += v[k].z; acc.w += v[k].w;
        }
    } else {
        for (int l = start + rl; l < end; l += 4) {
            float4 v0 = base[(size_t)l * (E_ / 4)];
            acc.x += v0.x; acc.y += v0.y; acc.z += v0.z; acc.w += v0.w;
        }
    }
    __shared__ __align__(16) float4 red[4][64];
    red[rl][cl] = acc;
    __syncthreads();
    if (rl == 0) {
        float4 a = red[0][cl], p = red[1][cl], q = red[2][cl], r = red[3][cl];
        float4 s;
        s.x = a.x + p.x + q.x + r.x;
        s.y = a.y + p.y + q.y + r.y;
        s.z = a.z + p.z + q.z + r.z;
        s.w = a.w + p.w + q.w + r.w;
        ((float4*)g_part1[si][b])[cl] = s;
    }
}

// =====================================================================
// K1b: one block per batch — X -> s = Wq X + len*bq ; t = Wk^T s ; c = s.bk
// Wq matvec is WARP-COOPERATIVE: warp w computes f = w, w+8, ..., w+248;
// lanes split the 256-wide dot (coalesced row reads), shuffle-reduce.
// =====================================================================
__global__ void __launch_bounds__(256) k1_combine(
    const int* __restrict__ lengths,
    const float* __restrict__ Wq, const float* __restrict__ bq,
    const float* __restrict__ Wk, const float* __restrict__ bk)
{
    const int b = blockIdx.x, tid = threadIdx.x;
    const int warp = tid >> 5, lane = tid & 31;
    const int len = lengths[b];
    const int nact = min(SPLITS, (len + CHUNK - 1) / CHUNK);

    __shared__ __align__(16) float sX[E_];
    __shared__ float sS[E_];
    {
        float xv = 0.f;
#pragma unroll 8
        for (int s = 0; s < nact; ++s) xv += g_part1[s][b][tid];
        sX[tid] = xv;
    }
    __syncthreads();

    // s[f] = Wq[f,:].X + len*bq[f]  — warp-per-output, coalesced
    {
        const float4* wq4 = (const float4*)Wq;
        const float4* x4  = (const float4*)sX;
        const float4 xa = x4[lane];        // lane's slice of X (elems 4l..4l+3)
        const float4 xb = x4[32 + lane];   // elems 128+4l..
        const float flen = (float)len;
#pragma unroll
        for (int k = 0; k < 32; k += 4) {
            const int f0 = warp + 8 * (k + 0);
            const int f1 = warp + 8 * (k + 1);
            const int f2 = warp + 8 * (k + 2);
            const int f3 = warp + 8 * (k + 3);
            float p0 = dot4(wq4[f0 * 64 + lane], xa) + dot4(wq4[f0 * 64 + 32 + lane], xb);
            float p1 = dot4(wq4[f1 * 64 + lane], xa) + dot4(wq4[f1 * 64 + 32 + lane], xb);
            float p2 = dot4(wq4[f2 * 64 + lane], xa) + dot4(wq4[f2 * 64 + 32 + lane], xb);
            float p3 = dot4(wq4[f3 * 64 + lane], xa) + dot4(wq4[f3 * 64 + 32 + lane], xb);
#pragma unroll
            for (int off = 16; off > 0; off >>= 1) {
                p0 += __shfl_xor_sync(0xffffffffu, p0, off);
                p1 += __shfl_xor_sync(0xffffffffu, p1, off);
                p2 += __shfl_xor_sync(0xffffffffu, p2, off);
                p3 += __shfl_xor_sync(0xffffffffu, p3, off);
            }
            if (lane == 0) {
                sS[f0] = p0 + flen * bq[f0];
                sS[f1] = p1 + flen * bq[f1];
                sS[f2] = p2 + flen * bq[f2];
                sS[f3] = p3 + flen * bq[f3];
            }
        }
    }
    __syncthreads();

    // t[e] = sum_f s[f]*Wk[f,e] — already coalesced (threads span e)
    {
        const int eg = tid & 63;
        const int fg = tid >> 6;
        const float4* wk4 = (const float4*)Wk;
        float4 tv = make_float4(0.f, 0.f, 0.f, 0.f);
#pragma unroll 8
        for (int j = 0; j < 64; ++j) {
            const int f = fg * 64 + j;
            const float sv = sS[f];
            float4 wv = wk4[(size_t)f * (E_ / 4) + eg];
            tv.x += sv * wv.x; tv.y += sv * wv.y; tv.z += sv * wv.z; tv.w += sv * wv.w;
        }
        __shared__ __align__(16) float4 tpart[4][64];
        tpart[fg][eg] = tv;
        __syncthreads();
        if (tid < 64) {
            float4 a = tpart[0][tid], p = tpart[1][tid], q = tpart[2][tid], r = tpart[3][tid];
            float4 t0;
            t0.x = a.x + p.x + q.x + r.x;
            t0.y = a.y + p.y + q.y + r.y;
            t0.z = a.z + p.z + q.z + r.z;
            t0.w = a.w + p.w + q.w + r.w;
            ((float4*)(g_t + b * E_))[tid] = t0;
        }
    }

    // c = s . bk
    __syncthreads();
    sX[tid] = sS[tid] * bk[tid];
    __syncthreads();
    for (int s = E_ / 2; s > 0; s >>= 1) {
        if (tid < s) sX[tid] += sX[tid + s];
        __syncthreads();
    }
    if (tid == 0) g_c[b] = sX[0];
}

// =====================================================================
// K2: stage chunk to SMEM (MLP=8/thread), compute w + y partials. No sync.
// =====================================================================
__global__ void __launch_bounds__(256) k2_stream(
    const float* __restrict__ x, const int* __restrict__ lengths)
{
    const int si = blockIdx.x, b = blockIdx.y, tid = threadIdx.x;
    const int warp = tid >> 5, lane = tid & 31;
    const int len = lengths[b];
    const int start = si * CHUNK;
    const int end = min(start + CHUNK, len);
    const int rows = end - start;
    if (rows <= 0) return;

    __shared__ __align__(16) float sx[CHUNK * E_];   // 32 KB staged tile
    __shared__ float shw[CHUNK];

    // ---- stage: 2048 float4, 8 independent loads per thread ----
    {
        const float4* src = (const float4*)(x + ((size_t)b * L_ + start) * E_);
        float4* dst = (float4*)sx;
#pragma unroll
        for (int i = 0; i < 8; ++i) {
            const int idx = tid + 256 * i;        // [0, 2048)
            const int row = idx >> 6;             // 64 float4 per row
            float4 v = make_float4(0.f, 0.f, 0.f, 0.f);
            if (row < rows) v = src[idx];
            dst[idx] = v;                         // zero-pad invalid rows
        }
    }
    __syncthreads();

    // ---- w-dots from SMEM: warp wp handles rows wp, wp+8, wp+16, wp+24 ----
    {
        const float4* t4 = (const float4*)(g_t + b * E_);
        const float4 ta = t4[lane];
        const float4 tb = t4[32 + lane];
        const float c = g_c[b];
        float p0, p1, p2, p3;
        {
            const float4* r0 = (const float4*)(sx + (warp +  0) * E_);
            const float4* r1 = (const float4*)(sx + (warp +  8) * E_);
            const float4* r2 = (const float4*)(sx + (warp + 16) * E_);
            const float4* r3 = (const float4*)(sx + (warp + 24) * E_);
            p0 = dot4(r0[lane], ta) + dot4(r0[32 + lane], tb);
            p1 = dot4(r1[lane], ta) + dot4(r1[32 + lane], tb);
            p2 = dot4(r2[lane], ta) + dot4(r2[32 + lane], tb);
            p3 = dot4(r3[lane], ta) + dot4(r3[32 + lane], tb);
        }
#pragma unroll
        for (int off = 16; off > 0; off >>= 1) {   // 4 interleaved chains
            p0 += __shfl_xor_sync(0xffffffffu, p0, off);
            p1 += __shfl_xor_sync(0xffffffffu, p1, off);
            p2 += __shfl_xor_sync(0xffffffffu, p2, off);
            p3 += __shfl_xor_sync(0xffffffffu, p3, off);
        }
        if (lane == 0) {
            shw[warp +  0] = p0 + c;
            shw[warp +  8] = p1 + c;
            shw[warp + 16] = p2 + c;
            shw[warp + 24] = p3 + c;
        }
    }
    __syncthreads();

    // ---- y[e] = sum_l w_l * x_l[e]; thread owns column e = tid ----
    {
        float y = 0.f;
#pragma unroll
        for (int l = 0; l < CHUNK; ++l)
            y += shw[l] * sx[l * E_ + tid];       // invalid rows: sx==0
        g_part2[si][b][tid] = y;
    }
    // ---- partial sum of w over VALID rows (warp 0; CHUNK == 32 lanes) ----
    if (warp == 0) {
        float v = (lane < rows) ? shw[lane] : 0.f;
#pragma unroll
        for (int off = 16; off > 0; off >>= 1)
            v += __shfl_xor_sync(0xffffffffu, v, off);
        if (lane == 0) g_Wpart[si][b] = v;
    }
}

// =====================================================================
// K2b: one block per batch — out[b] = (Wv y + W*bv) / L
// Wv matvec is WARP-COOPERATIVE (coalesced), same scheme as k1_combine.
// =====================================================================
__global__ void __launch_bounds__(256) k2_combine(
    const int* __restrict__ lengths,
    const float* __restrict__ Wv, const float* __restrict__ bv,
    float* __restrict__ out)
{
    const int b = blockIdx.x, tid = threadIdx.x;
    const int warp = tid >> 5, lane = tid & 31;
    const int len = lengths[b];
    const int nact = min(SPLITS, (len + CHUNK - 1) / CHUNK);

    __shared__ __align__(16) float ys[E_];
    __shared__ float wtot;
    {
        float yv = 0.f;
#pragma unroll 8
        for (int s = 0; s < nact; ++s) yv += g_part2[s][b][tid];
        ys[tid] = yv;
    }
    if (warp == 0) {
        float W = 0.f;
        for (int s = lane; s < nact; s += 32) W += g_Wpart[s][b];
#pragma unroll
        for (int off = 16; off > 0; off >>= 1)
            W += __shfl_xor_sync(0xffffffffu, W, off);
        if (lane == 0) wtot = W;
    }
    __syncthreads();

    // out[f] = (Wv[f,:].y + W*bv[f]) / L — warp-per-output, coalesced
    {
        const float4* wv4 = (const float4*)Wv;
        const float4* y4  = (const float4*)ys;
        const float4 ya = y4[lane];
        const float4 yb = y4[32 + lane];
        const float W = wtot;
        const float invL = 1.0f / (float)L_;
#pragma unroll
        for (int k = 0; k < 32; k += 4) {
            const int f0 = warp + 8 * (k + 0);
            const int f1 = warp + 8 * (k + 1);
            const int f2 = warp + 8 * (k + 2);
            const int f3 = warp + 8 * (k + 3);
            float p0 = dot4(wv4[f0 * 64 + lane], ya) + dot4(wv4[f0 * 64 + 32 + lane], yb);
            float p1 = dot4(wv4[f1 * 64 + lane], ya) + dot4(wv4[f1 * 64 + 32 + lane], yb);
            float p2 = dot4(wv4[f2 * 64 + lane], ya) + dot4(wv4[f2 * 64 + 32 + lane], yb);
            float p3 = dot4(wv4[f3 * 64 + lane], ya) + dot4(wv4[f3 * 64 + 32 + lane], yb);
#pragma unroll
            for (int off = 16; off > 0; off >>= 1) {
                p0 += __shfl_xor_sync(0xffffffffu, p0, off);
                p1 += __shfl_xor_sync(0xffffffffu, p1, off);
                p2 += __shfl_xor_sync(0xffffffffu, p2, off);
                p3 += __shfl_xor_sync(0xffffffffu, p3, off);
            }
            if (lane == 0) {
                out[b * E_ + f0] = (p0 + W * bv[f0]) * invL;
                out[b * E_ + f1] = (p1 + W * bv[f1]) * invL;
                out[b * E_ + f2] = (p2 + W * bv[f2]) * invL;
                out[b * E_ + f3] = (p3 + W * bv[f3]) * invL;
            }
        }
    }
}

extern "C" void kernel_launch(void* const* d_in, const int* in_sizes, int n_in,
                              void* d_out, int out_size) {
    const float* x       = (const float*)d_in[0];
    const int*   lengths = (const int*)d_in[1];
    const float* Wq      = (const float*)d_in[2];
    const float* bq      = (const float*)d_in[3];
    const float* Wk      = (const float*)d_in[4];
    const float* bk      = (const float*)d_in[5];
    const float* Wv      = (const float*)d_in[6];
    const float* bv      = (const float*)d_in[7];
    float* out = (float*)d_out;

    k1_stream <<<dim3(SPLITS, B_), 256>>>(x, lengths);
    k1_combine<<<B_, 256>>>(lengths, Wq, bq, Wk, bk);
    k2_stream <<<dim3(SPLITS, B_), 256>>>(x, lengths);
    k2_combine<<<B_, 256>>>(lengths, Wv, bv, out);
}